// round 3
// baseline (speedup 1.0000x reference)
#include <cuda_runtime.h>
#include <cuda_bf16.h>
#include <math.h>
#include <stdint.h>

// Problem constants (fixed by the dataset)
#define H_HEADS   32
#define KV_HEADS  8
#define DIM       128
#define PAGE      16
#define TOPK      256
#define GRP       4            // H / KV
#define HID       4096         // H*DIM
#define QKV_N     6144         // 4096 q + 1024 k + 1024 v
#define SPLIT     32
#define MAXPAGES  2048
#define NCHUNK    16           // flash-decode chunks per head
#define PPC       16           // pages per chunk (TOPK / NCHUNK)
#define TPC       256          // tokens per chunk (PPC*PAGE)

// libdevice accurate powf, immune to -use_fast_math remapping
extern "C" __device__ float __nv_powf(float, float);

// -------- device scratch (no allocations allowed) --------
// NOTE: device symbols are ONLY referenced inside kernels (never passed as
// kernel args from host -- host-side symbol address is the host shadow, and
// on GB300 ATS makes stores to it succeed silently -> silent corruption).
__device__ float g_partial[SPLIT * QKV_N];
__device__ float g_qkv[QKV_N];                       // [0,4096)=q, [4096,5120)=k, [5120,6144)=v
__device__ float g_scores[H_HEADS * MAXPAGES];
__device__ int   g_topk[H_HEADS * TOPK];
__device__ float g_m[H_HEADS * NCHUNK];
__device__ float g_l[H_HEADS * NCHUNK];
__device__ float g_acc[H_HEADS * NCHUNK * DIM];
__device__ float g_attnout[HID];

// ======================== split-K GEMV ========================
// y[j] = sum_i x[i] * W[i*N + j], K=4096 split into 32 chunks of 128.
template <bool X_FROM_ATTN>
__global__ void gemv_partial_k(const float* __restrict__ W, const float* __restrict__ x,
                               int N, int colOff) {
    __shared__ float xs[128];
    int tid = threadIdx.x;
    int cb = blockIdx.y * 128;           // chunk base in K (K=4096)
    if (tid < 128) xs[tid] = X_FROM_ATTN ? g_attnout[cb + tid] : x[cb + tid];
    __syncthreads();
    int j = blockIdx.x * 256 + tid;
    const float* w = W + (size_t)cb * N + j;
    float acc = 0.f;
#pragma unroll 8
    for (int i = 0; i < 128; ++i) acc += xs[i] * w[(size_t)i * N];
    g_partial[blockIdx.y * QKV_N + colOff + j] = acc;
}

__global__ void gemv_reduce_qkv_k() {
    int j = blockIdx.x * 256 + threadIdx.x;
    float s = 0.f;
#pragma unroll
    for (int c = 0; c < SPLIT; ++c) s += g_partial[c * QKV_N + j];
    g_qkv[j] = s;
}

__global__ void gemv_reduce_out_k(float* __restrict__ out) {
    int j = blockIdx.x * 256 + threadIdx.x;
    float s = 0.f;
#pragma unroll
    for (int c = 0; c < SPLIT; ++c) s += g_partial[c * QKV_N + j];
    out[j] = s;
}

// ======================== RoPE ========================
// Bit-replicates reference (XLA-GPU f32) rounding chain:
//   inv = 1.0f / __nv_powf(10000f, j/64f)   (libdevice powf + f32 reciprocal)
//   ang = fl32(32767f * inv)                (f32 multiply)
//   cos/sin of that exact f32 angle (double trig; diff vs __nv_cosf ~1e-7, unamplified)
__global__ void rope_k(int past) {
    int g = blockIdx.x * blockDim.x + threadIdx.x;
    if (g >= 40 * 64) return;
    int row = g >> 6, j = g & 63;
    int base = (row < 32) ? row * 128 : 4096 + (row - 32) * 128;
    float e    = (float)j / 64.0f;
    float p    = __nv_powf(10000.0f, e);
    float invf = 1.0f / p;
    float ang  = (float)past * invf;         // f32 multiply, matches reference
    double a = (double)ang;
    float c = (float)cos(a), s = (float)sin(a);
    float xl = g_qkv[base + j], xh = g_qkv[base + j + 64];
    g_qkv[base + j]      = xl * c - xh * s;
    g_qkv[base + j + 64] = xh * c + xl * s;
}

// ======================== page min/max + Quest score ========================
// One block per page. score[h,p] = sum_d q[h,d] * (q>=0 ? kmax : kmin)
__global__ void score_k(const float* __restrict__ kc, int np) {
    int p = blockIdx.x;
    int tid = threadIdx.x;
    if (p == np - 1) {                       // last page forced selected
        if (tid < H_HEADS) g_scores[tid * np + p] = INFINITY;
        return;
    }
    __shared__ float qs[HID];
    __shared__ float kmx[KV_HEADS * DIM];
    __shared__ float kmn[KV_HEADS * DIM];
    for (int i = tid; i < HID; i += 256) qs[i] = g_qkv[i];
#pragma unroll
    for (int rep = 0; rep < 4; ++rep) {
        int pr = rep * 256 + tid;            // (kv,d) pair, 1024 total
        const float* base = kc + (size_t)p * PAGE * (KV_HEADS * DIM) + pr;
        float mx = base[0], mn = mx;
#pragma unroll
        for (int t = 1; t < PAGE; ++t) {
            float v = base[(size_t)t * (KV_HEADS * DIM)];
            mx = fmaxf(mx, v); mn = fminf(mn, v);
        }
        kmx[pr] = mx; kmn[pr] = mn;
    }
    __syncthreads();
    int h = tid >> 3, seg = tid & 7;
    int kv = h >> 2;
    float sum = 0.f;
    int db = seg * 16;
#pragma unroll
    for (int d = 0; d < 16; ++d) {
        float qv = qs[h * DIM + db + d];
        float km = kmx[kv * DIM + db + d];
        float kn = kmn[kv * DIM + db + d];
        sum += qv * (qv >= 0.f ? km : kn);
    }
    sum += __shfl_down_sync(0xffffffffu, sum, 4);
    sum += __shfl_down_sync(0xffffffffu, sum, 2);
    sum += __shfl_down_sync(0xffffffffu, sum, 1);
    if (seg == 0) g_scores[h * np + p] = sum;
}

// ======================== exact top-k via bitonic sort ========================
// Keys: monotone-f32 in hi 32b, (np-1-idx) in lo 32b; bit-inverted, ascending sort.
// First 256 = largest scores, ties broken by lowest index (matches jax top_k).
__global__ void topk_k(int np) {
    int h = blockIdx.x;
    int tid = threadIdx.x;                   // 1024 threads
    __shared__ unsigned long long keys[MAXPAGES];
    for (int i = tid; i < MAXPAGES; i += 1024) {
        unsigned long long kk;
        if (i < np) {
            float f = g_scores[h * np + i];
            unsigned u = __float_as_uint(f);
            u = (u & 0x80000000u) ? ~u : (u | 0x80000000u);
            kk = ~(((unsigned long long)u << 32) | (unsigned)(np - 1 - i));
        } else {
            kk = 0xFFFFFFFFFFFFFFFFull;
        }
        keys[i] = kk;
    }
    __syncthreads();
    for (int k = 2; k <= MAXPAGES; k <<= 1) {
        for (int j = k >> 1; j > 0; j >>= 1) {
            for (int i = tid; i < MAXPAGES; i += 1024) {
                int ixj = i ^ j;
                if (ixj > i) {
                    bool up = ((i & k) == 0);
                    unsigned long long a = keys[i], b = keys[ixj];
                    if ((a > b) == up) { keys[i] = b; keys[ixj] = a; }
                }
            }
            __syncthreads();
        }
    }
    if (tid < TOPK) {
        unsigned long long orig = ~keys[tid];
        int idx = np - 1 - (int)(orig & 0xFFFFFFFFull);
        g_topk[h * TOPK + tid] = idx;
    }
}

// ======================== flash-decode partial ========================
// Block = (head, chunk). 256 tokens per chunk. Warp-collective dot products.
__global__ void attn_partial_k(const float* __restrict__ kc, const float* __restrict__ vc,
                               int past) {
    int b = blockIdx.x;
    int h = b >> 4, chunk = b & 15;
    int kv = h >> 2;
    int tid = threadIdx.x, w = tid >> 5, lane = tid & 31;
    __shared__ float sc[TPC];
    __shared__ float redm[8];
    __shared__ float redl[8];
    __shared__ float accbuf[8 * DIM];

    float4 qv = *(const float4*)(g_qkv + h * DIM + lane * 4);
    const int* tk = g_topk + h * TOPK + chunk * PPC;

    // --- scores ---
    for (int s = 0; s < 32; ++s) {
        int tw = w * 32 + s;
        int page = tk[tw >> 4];
        int tok = page * PAGE + (tw & 15);
        const float4* kp = (tok == past)
            ? (const float4*)(g_qkv + 4096 + kv * DIM)
            : (const float4*)(kc + ((size_t)tok * KV_HEADS + kv) * DIM);
        float4 k4 = kp[lane];
        float d = qv.x * k4.x + qv.y * k4.y + qv.z * k4.z + qv.w * k4.w;
        d += __shfl_xor_sync(0xffffffffu, d, 16);
        d += __shfl_xor_sync(0xffffffffu, d, 8);
        d += __shfl_xor_sync(0xffffffffu, d, 4);
        d += __shfl_xor_sync(0xffffffffu, d, 2);
        d += __shfl_xor_sync(0xffffffffu, d, 1);
        if (lane == 0) sc[tw] = d * 0.08838834764831844f;   // 1/sqrt(128)
    }
    __syncthreads();

    // --- block max ---
    float v = sc[tid];
    float m = v;
#pragma unroll
    for (int o = 16; o; o >>= 1) m = fmaxf(m, __shfl_xor_sync(0xffffffffu, m, o));
    if (lane == 0) redm[w] = m;
    __syncthreads();
    if (tid == 0) {
        float mm = redm[0];
#pragma unroll
        for (int i = 1; i < 8; ++i) mm = fmaxf(mm, redm[i]);
        redm[0] = mm;
    }
    __syncthreads();
    float bm = redm[0];

    // --- exp + row sum ---
    float e = __expf(v - bm);
    sc[tid] = e;
    float l = e;
#pragma unroll
    for (int o = 16; o; o >>= 1) l += __shfl_xor_sync(0xffffffffu, l, o);
    if (lane == 0) redl[w] = l;
    __syncwarp();   // sc[w*32..w*32+31] must be visible within the warp below

    // --- V accumulate (each warp over its own 32 tokens; sc[tw] is warp-local) ---
    float4 acc = make_float4(0.f, 0.f, 0.f, 0.f);
    for (int s = 0; s < 32; ++s) {
        int tw = w * 32 + s;
        int page = tk[tw >> 4];
        int tok = page * PAGE + (tw & 15);
        const float4* vp = (tok == past)
            ? (const float4*)(g_qkv + 5120 + kv * DIM)
            : (const float4*)(vc + ((size_t)tok * KV_HEADS + kv) * DIM);
        float4 v4 = vp[lane];
        float ee = sc[tw];
        acc.x += ee * v4.x; acc.y += ee * v4.y;
        acc.z += ee * v4.z; acc.w += ee * v4.w;
    }
    *(float4*)(accbuf + w * DIM + lane * 4) = acc;
    __syncthreads();
    if (tid < DIM) {
        float s = 0.f;
#pragma unroll
        for (int ww = 0; ww < 8; ++ww) s += accbuf[ww * DIM + tid];
        g_acc[(h * NCHUNK + chunk) * DIM + tid] = s;
    }
    if (tid == 0) {
        float L = 0.f;
#pragma unroll
        for (int i = 0; i < 8; ++i) L += redl[i];
        g_m[h * NCHUNK + chunk] = bm;
        g_l[h * NCHUNK + chunk] = L;
    }
}

// ======================== flash-decode combine ========================
__global__ void attn_combine_k() {
    int h = blockIdx.x;
    int d = threadIdx.x;                     // 128
    float M = -INFINITY;
#pragma unroll
    for (int c = 0; c < NCHUNK; ++c) M = fmaxf(M, g_m[h * NCHUNK + c]);
    float L = 0.f, acc = 0.f;
#pragma unroll
    for (int c = 0; c < NCHUNK; ++c) {
        float f = __expf(g_m[h * NCHUNK + c] - M);
        L += f * g_l[h * NCHUNK + c];
        acc += f * g_acc[(h * NCHUNK + c) * DIM + d];
    }
    g_attnout[h * DIM + d] = acc / L;
}

// ======================== launcher ========================
extern "C" void kernel_launch(void* const* d_in, const int* in_sizes, int n_in,
                              void* d_out, int out_size) {
    const float* x  = (const float*)d_in[0];
    const float* kc = (const float*)d_in[1];
    const float* vc = (const float*)d_in[2];
    const float* Wq = (const float*)d_in[3];
    const float* Wk = (const float*)d_in[4];
    const float* Wv = (const float*)d_in[5];
    const float* Wo = (const float*)d_in[6];
    float* out = (float*)d_out;

    int past = in_sizes[1] / (KV_HEADS * DIM);   // 32767
    int np   = (past + 1) / PAGE;                // 2048

    // QKV projections (split-K GEMV)
    gemv_partial_k<false><<<dim3(HID / 256, SPLIT), 256>>>(Wq, x, HID, 0);
    gemv_partial_k<false><<<dim3(1024 / 256, SPLIT), 256>>>(Wk, x, 1024, 4096);
    gemv_partial_k<false><<<dim3(1024 / 256, SPLIT), 256>>>(Wv, x, 1024, 5120);
    gemv_reduce_qkv_k<<<QKV_N / 256, 256>>>();

    // RoPE on q and k
    rope_k<<<10, 256>>>(past);

    // Quest page scores (streams full k_cache)
    score_k<<<np, 256>>>(kc, np);

    // Exact top-256 per head
    topk_k<<<H_HEADS, 1024>>>(np);

    // Flash-decode over selected pages
    attn_partial_k<<<H_HEADS * NCHUNK, 256>>>(kc, vc, past);
    attn_combine_k<<<H_HEADS, 128>>>();

    // Output projection
    gemv_partial_k<true><<<dim3(HID / 256, SPLIT), 256>>>(Wo, nullptr, HID, 0);
    gemv_reduce_out_k<<<HID / 256, 256>>>(out);
}

// round 4
// speedup vs baseline: 1.2127x; 1.2127x over previous
#include <cuda_runtime.h>
#include <cuda_bf16.h>
#include <math.h>
#include <stdint.h>

#define H_HEADS   32
#define KV_HEADS  8
#define DIM       128
#define PAGE      16
#define TOPK      256
#define HID       4096
#define QKV_N     6144         // 4096 q + 1024 k + 1024 v
#define SPLIT     128          // K-chunks of 32 rows
#define MAXPAGES  2048
#define NCHUNK    32           // flash-decode chunks per head
#define PPC       8            // pages per chunk
#define TPC       128          // tokens per chunk

extern "C" __device__ float __nv_powf(float, float);

// -------- device scratch (symbols only referenced inside kernels!) --------
__device__ float g_partial[SPLIT * QKV_N];
__device__ float g_qkv[QKV_N];                 // [0,4096)=q, [4096,5120)=k, [5120,6144)=v
__device__ float g_scores[H_HEADS * MAXPAGES];
__device__ int   g_topk[H_HEADS * TOPK];
__device__ float g_m[H_HEADS * NCHUNK];
__device__ float g_l[H_HEADS * NCHUNK];
__device__ float g_acc[H_HEADS * NCHUNK * DIM];
__device__ float g_attnout[HID];

// ======================== fused QKV split-K GEMV (float4) ========================
// blocks [0,512): Wq (N4=1024, 4 col-blocks x 128 chunks)
// blocks [512,640): Wk ; [640,768): Wv (N4=256, 1 col-block x 128 chunks)
__global__ void gemv_qkv_k(const float* __restrict__ Wq, const float* __restrict__ Wk,
                           const float* __restrict__ Wv, const float* __restrict__ x) {
    int b = blockIdx.x, tid = threadIdx.x;
    const float* W; int N4, xb, chunk, colOff4;
    if (b < 512)      { W = Wq; N4 = 1024; xb = b & 3; chunk = b >> 2;  colOff4 = 0; }
    else if (b < 640) { W = Wk; N4 = 256;  xb = 0;     chunk = b - 512; colOff4 = 1024; }
    else              { W = Wv; N4 = 256;  xb = 0;     chunk = b - 640; colOff4 = 1280; }
    __shared__ float xs[32];
    if (tid < 32) xs[tid] = x[chunk * 32 + tid];
    __syncthreads();
    int j4 = xb * 256 + tid;
    const float4* w4 = (const float4*)W + (size_t)(chunk * 32) * N4 + j4;
    float4 a = make_float4(0.f, 0.f, 0.f, 0.f);
#pragma unroll
    for (int i = 0; i < 32; ++i) {
        float4 wv = w4[(size_t)i * N4];
        float xv = xs[i];
        a.x = fmaf(xv, wv.x, a.x); a.y = fmaf(xv, wv.y, a.y);
        a.z = fmaf(xv, wv.z, a.z); a.w = fmaf(xv, wv.w, a.w);
    }
    ((float4*)g_partial)[chunk * (QKV_N / 4) + colOff4 + j4] = a;
}

// ======================== Wo split-K GEMV (x = g_attnout) ========================
__global__ void gemv_o_k(const float* __restrict__ Wo) {
    int b = blockIdx.x, tid = threadIdx.x;
    int xb = b & 3, chunk = b >> 2;
    __shared__ float xs[32];
    if (tid < 32) xs[tid] = g_attnout[chunk * 32 + tid];
    __syncthreads();
    int j4 = xb * 256 + tid;
    const float4* w4 = (const float4*)Wo + (size_t)(chunk * 32) * 1024 + j4;
    float4 a = make_float4(0.f, 0.f, 0.f, 0.f);
#pragma unroll
    for (int i = 0; i < 32; ++i) {
        float4 wv = w4[(size_t)i * 1024];
        float xv = xs[i];
        a.x = fmaf(xv, wv.x, a.x); a.y = fmaf(xv, wv.y, a.y);
        a.z = fmaf(xv, wv.z, a.z); a.w = fmaf(xv, wv.w, a.w);
    }
    ((float4*)g_partial)[chunk * (QKV_N / 4) + j4] = a;
}

// ======================== reduce partials + fused RoPE ========================
// 24 blocks x 256. RoPE replicates reference f32 rounding chain:
// inv = 1/__nv_powf(1e4, j/64) ; ang = fl32(past*inv) ; cos/sin via double trig.
__global__ void reduce_rope_k(int past) {
    int tid = threadIdx.x;
    int e = blockIdx.x * 256 + tid;
    __shared__ float redsum[256];
    __shared__ float ctab[64], stab[64];
    if (tid < 64) {
        float ee = (float)tid / 64.0f;
        float p = __nv_powf(10000.0f, ee);
        float invf = 1.0f / p;
        float ang = (float)past * invf;
        double aa = (double)ang;
        ctab[tid] = (float)cos(aa);
        stab[tid] = (float)sin(aa);
    }
    float s = 0.f;
#pragma unroll 16
    for (int c = 0; c < SPLIT; ++c) s += g_partial[c * QKV_N + e];
    redsum[tid] = s;
    __syncthreads();
    int row = e >> 7, col = e & 127;
    float outv = s;
    if (row < 40) {                       // q rows 0-31, k rows 32-39
        float partner = redsum[tid ^ 64];
        float c = ctab[col & 63], sn = stab[col & 63];
        outv = (col < 64) ? (s * c - partner * sn) : (s * c + partner * sn);
    }
    g_qkv[e] = outv;
}

// ======================== reduce partials -> output ========================
__global__ void reduce_out_k(float* __restrict__ out) {
    int j = blockIdx.x * 256 + threadIdx.x;
    float s = 0.f;
#pragma unroll 16
    for (int c = 0; c < SPLIT; ++c) s += g_partial[c * QKV_N + j];
    out[j] = s;
}

// ======================== page min/max + Quest score (float4) ========================
__global__ void score_k(const float* __restrict__ kc, int np) {
    int p = blockIdx.x;
    int tid = threadIdx.x;
    if (p == np - 1) {
        if (tid < H_HEADS) g_scores[tid * np + p] = INFINITY;
        return;
    }
    __shared__ float qs[HID];
    __shared__ float kmx[KV_HEADS * DIM];
    __shared__ float kmn[KV_HEADS * DIM];
    for (int i = tid; i < HID / 4; i += 256)
        ((float4*)qs)[i] = ((const float4*)g_qkv)[i];
    {
        const float4* base4 = (const float4*)(kc + (size_t)p * PAGE * 1024) + tid;
        float4 v0 = base4[0];
        float4 mx = v0, mn = v0;
#pragma unroll
        for (int t = 1; t < PAGE; ++t) {
            float4 v = base4[t * 256];
            mx.x = fmaxf(mx.x, v.x); mn.x = fminf(mn.x, v.x);
            mx.y = fmaxf(mx.y, v.y); mn.y = fminf(mn.y, v.y);
            mx.z = fmaxf(mx.z, v.z); mn.z = fminf(mn.z, v.z);
            mx.w = fmaxf(mx.w, v.w); mn.w = fminf(mn.w, v.w);
        }
        ((float4*)kmx)[tid] = mx;
        ((float4*)kmn)[tid] = mn;
    }
    __syncthreads();
    int h = tid >> 3, seg = tid & 7;
    int kv = h >> 2;
    float sum = 0.f;
    int db = seg * 16;
#pragma unroll
    for (int d = 0; d < 16; ++d) {
        float qv = qs[h * DIM + db + d];
        float km = kmx[kv * DIM + db + d];
        float kn = kmn[kv * DIM + db + d];
        sum += qv * (qv >= 0.f ? km : kn);
    }
    sum += __shfl_down_sync(0xffffffffu, sum, 4);
    sum += __shfl_down_sync(0xffffffffu, sum, 2);
    sum += __shfl_down_sync(0xffffffffu, sum, 1);
    if (seg == 0) g_scores[h * np + p] = sum;
}

// ======================== exact top-k via bitonic sort ========================
__global__ void topk_k(int np) {
    int h = blockIdx.x;
    int tid = threadIdx.x;                   // 1024 threads
    __shared__ unsigned long long keys[MAXPAGES];
    for (int i = tid; i < MAXPAGES; i += 1024) {
        unsigned long long kk;
        if (i < np) {
            float f = g_scores[h * np + i];
            unsigned u = __float_as_uint(f);
            u = (u & 0x80000000u) ? ~u : (u | 0x80000000u);
            kk = ~(((unsigned long long)u << 32) | (unsigned)(np - 1 - i));
        } else {
            kk = 0xFFFFFFFFFFFFFFFFull;
        }
        keys[i] = kk;
    }
    __syncthreads();
    for (int k = 2; k <= MAXPAGES; k <<= 1) {
        for (int j = k >> 1; j > 0; j >>= 1) {
            for (int i = tid; i < MAXPAGES; i += 1024) {
                int ixj = i ^ j;
                if (ixj > i) {
                    bool up = ((i & k) == 0);
                    unsigned long long a = keys[i], b = keys[ixj];
                    if ((a > b) == up) { keys[i] = b; keys[ixj] = a; }
                }
            }
            __syncthreads();
        }
    }
    if (tid < TOPK) {
        unsigned long long orig = ~keys[tid];
        int idx = np - 1 - (int)(orig & 0xFFFFFFFFull);
        g_topk[h * TOPK + tid] = idx;
    }
}

// ======================== flash-decode partial ========================
// Block = (head, chunk): 128 tokens. Score: 4 lanes/token, 8 tokens per warp-iter.
__global__ void attn_partial_k(const float* __restrict__ kc, const float* __restrict__ vc,
                               int past) {
    int b = blockIdx.x;
    int h = b >> 5, chunk = b & 31;
    int kv = h >> 2;
    int tid = threadIdx.x, w = tid >> 5, lane = tid & 31;
    __shared__ float sc[TPC];
    __shared__ float redm[8];
    __shared__ float redl[8];
    __shared__ float accbuf[8 * DIM];

    const int* tk = g_topk + h * TOPK + chunk * PPC;   // 8 pages = 128 tokens

    // ---- scores: warp w owns tokens [w*16, w*16+16), 8 tokens per iteration ----
    {
        int sub = lane & 3, tg = lane >> 2;
        float4 q4[8];
        const float4* qp = (const float4*)(g_qkv + h * DIM);
#pragma unroll
        for (int m = 0; m < 8; ++m) q4[m] = qp[sub + 4 * m];
#pragma unroll
        for (int t = 0; t < 2; ++t) {
            int tw = w * 16 + t * 8 + tg;
            int page = tk[tw >> 4];
            int tok = page * PAGE + (tw & 15);
            const float4* kp = (tok == past)
                ? (const float4*)(g_qkv + 4096 + kv * DIM)
                : (const float4*)(kc + ((size_t)tok * KV_HEADS + kv) * DIM);
            float d = 0.f;
#pragma unroll
            for (int m = 0; m < 8; ++m) {
                float4 k4 = kp[sub + 4 * m];
                d = fmaf(q4[m].x, k4.x, d); d = fmaf(q4[m].y, k4.y, d);
                d = fmaf(q4[m].z, k4.z, d); d = fmaf(q4[m].w, k4.w, d);
            }
            d += __shfl_xor_sync(0xffffffffu, d, 1);
            d += __shfl_xor_sync(0xffffffffu, d, 2);
            if (sub == 0) sc[tw] = d * 0.08838834764831844f;   // 1/sqrt(128)
        }
    }
    __syncthreads();

    // ---- softmax over 128 tokens (threads 0-127 own tokens) ----
    float v = (tid < TPC) ? sc[tid] : -INFINITY;
    float m = v;
#pragma unroll
    for (int o = 16; o; o >>= 1) m = fmaxf(m, __shfl_xor_sync(0xffffffffu, m, o));
    if (lane == 0) redm[w] = m;
    __syncthreads();
    if (tid == 0) {
        float mm = redm[0];
#pragma unroll
        for (int i = 1; i < 8; ++i) mm = fmaxf(mm, redm[i]);
        redm[0] = mm;
    }
    __syncthreads();
    float bm = redm[0];

    float e = (tid < TPC) ? __expf(v - bm) : 0.f;
    if (tid < TPC) sc[tid] = e;
    float l = e;
#pragma unroll
    for (int o = 16; o; o >>= 1) l += __shfl_xor_sync(0xffffffffu, l, o);
    if (lane == 0) redl[w] = l;
    __syncthreads();                          // sc[] written across warps

    // ---- V accumulate: warp w owns tokens [w*16, w*16+16) ----
    float4 acc = make_float4(0.f, 0.f, 0.f, 0.f);
#pragma unroll 4
    for (int s = 0; s < 16; ++s) {
        int tw = w * 16 + s;
        int page = tk[tw >> 4];
        int tok = page * PAGE + (tw & 15);
        const float4* vp = (tok == past)
            ? (const float4*)(g_qkv + 5120 + kv * DIM)
            : (const float4*)(vc + ((size_t)tok * KV_HEADS + kv) * DIM);
        float4 v4 = vp[lane];
        float ee = sc[tw];
        acc.x = fmaf(ee, v4.x, acc.x); acc.y = fmaf(ee, v4.y, acc.y);
        acc.z = fmaf(ee, v4.z, acc.z); acc.w = fmaf(ee, v4.w, acc.w);
    }
    *(float4*)(accbuf + w * DIM + lane * 4) = acc;
    __syncthreads();
    if (tid < DIM) {
        float s = 0.f;
#pragma unroll
        for (int ww = 0; ww < 8; ++ww) s += accbuf[ww * DIM + tid];
        g_acc[(h * NCHUNK + chunk) * DIM + tid] = s;
    }
    if (tid == 0) {
        float L = 0.f;
#pragma unroll
        for (int i = 0; i < 8; ++i) L += redl[i];
        g_m[h * NCHUNK + chunk] = bm;
        g_l[h * NCHUNK + chunk] = L;
    }
}

// ======================== flash-decode combine ========================
__global__ void attn_combine_k() {
    int h = blockIdx.x;
    int d = threadIdx.x;                     // 128
    float M = -INFINITY;
#pragma unroll
    for (int c = 0; c < NCHUNK; ++c) M = fmaxf(M, g_m[h * NCHUNK + c]);
    float L = 0.f, acc = 0.f;
#pragma unroll
    for (int c = 0; c < NCHUNK; ++c) {
        float f = __expf(g_m[h * NCHUNK + c] - M);
        L += f * g_l[h * NCHUNK + c];
        acc += f * g_acc[(h * NCHUNK + c) * DIM + d];
    }
    g_attnout[h * DIM + d] = acc / L;
}

// ======================== launcher ========================
extern "C" void kernel_launch(void* const* d_in, const int* in_sizes, int n_in,
                              void* d_out, int out_size) {
    const float* x  = (const float*)d_in[0];
    const float* kc = (const float*)d_in[1];
    const float* vc = (const float*)d_in[2];
    const float* Wq = (const float*)d_in[3];
    const float* Wk = (const float*)d_in[4];
    const float* Wv = (const float*)d_in[5];
    const float* Wo = (const float*)d_in[6];
    float* out = (float*)d_out;

    int past = in_sizes[1] / (KV_HEADS * DIM);   // 32767
    int np   = (past + 1) / PAGE;                // 2048

    gemv_qkv_k<<<768, 256>>>(Wq, Wk, Wv, x);
    reduce_rope_k<<<QKV_N / 256, 256>>>(past);
    score_k<<<np, 256>>>(kc, np);
    topk_k<<<H_HEADS, 1024>>>(np);
    attn_partial_k<<<H_HEADS * NCHUNK, 256>>>(kc, vc, past);
    attn_combine_k<<<H_HEADS, 128>>>();
    gemv_o_k<<<512, 256>>>(Wo);
    reduce_out_k<<<HID / 256, 256>>>(out);
}

// round 5
// speedup vs baseline: 1.3678x; 1.1279x over previous
#include <cuda_runtime.h>
#include <cuda_bf16.h>
#include <math.h>
#include <stdint.h>

#define H_HEADS   32
#define KV_HEADS  8
#define DIM       128
#define PAGE      16
#define TOPK      256
#define HID       4096
#define QKV_N     6144         // 4096 q + 1024 k + 1024 v
#define SPLIT     128          // K-chunks of 32 rows
#define MAXPAGES  2048
#define NCHUNK    32           // flash-decode chunks per head
#define PPC       8            // pages per chunk
#define TPC       128          // tokens per chunk

extern "C" __device__ float __nv_powf(float, float);

// -------- device scratch (symbols only referenced inside kernels!) --------
__device__ float g_partial[SPLIT * QKV_N];
__device__ float g_qkv[QKV_N];                 // [0,4096)=q, [4096,5120)=k, [5120,6144)=v
__device__ float g_scores[H_HEADS * MAXPAGES];
__device__ int   g_topk[H_HEADS * TOPK];
__device__ float g_m[H_HEADS * NCHUNK];
__device__ float g_l[H_HEADS * NCHUNK];
__device__ float g_acc[H_HEADS * NCHUNK * DIM];
__device__ float g_attnout[HID];

// ======================== fused QKV split-K GEMV (float4) ========================
__global__ void gemv_qkv_k(const float* __restrict__ Wq, const float* __restrict__ Wk,
                           const float* __restrict__ Wv, const float* __restrict__ x) {
    int b = blockIdx.x, tid = threadIdx.x;
    const float* W; int N4, xb, chunk, colOff4;
    if (b < 512)      { W = Wq; N4 = 1024; xb = b & 3; chunk = b >> 2;  colOff4 = 0; }
    else if (b < 640) { W = Wk; N4 = 256;  xb = 0;     chunk = b - 512; colOff4 = 1024; }
    else              { W = Wv; N4 = 256;  xb = 0;     chunk = b - 640; colOff4 = 1280; }
    __shared__ float xs[32];
    if (tid < 32) xs[tid] = x[chunk * 32 + tid];
    __syncthreads();
    int j4 = xb * 256 + tid;
    const float4* w4 = (const float4*)W + (size_t)(chunk * 32) * N4 + j4;
    float4 a = make_float4(0.f, 0.f, 0.f, 0.f);
#pragma unroll
    for (int i = 0; i < 32; ++i) {
        float4 wv = w4[(size_t)i * N4];
        float xv = xs[i];
        a.x = fmaf(xv, wv.x, a.x); a.y = fmaf(xv, wv.y, a.y);
        a.z = fmaf(xv, wv.z, a.z); a.w = fmaf(xv, wv.w, a.w);
    }
    ((float4*)g_partial)[chunk * (QKV_N / 4) + colOff4 + j4] = a;
}

// ======================== Wo split-K GEMV (x = g_attnout) ========================
__global__ void gemv_o_k(const float* __restrict__ Wo) {
    int b = blockIdx.x, tid = threadIdx.x;
    int xb = b & 3, chunk = b >> 2;
    __shared__ float xs[32];
    if (tid < 32) xs[tid] = g_attnout[chunk * 32 + tid];
    __syncthreads();
    int j4 = xb * 256 + tid;
    const float4* w4 = (const float4*)Wo + (size_t)(chunk * 32) * 1024 + j4;
    float4 a = make_float4(0.f, 0.f, 0.f, 0.f);
#pragma unroll
    for (int i = 0; i < 32; ++i) {
        float4 wv = w4[(size_t)i * 1024];
        float xv = xs[i];
        a.x = fmaf(xv, wv.x, a.x); a.y = fmaf(xv, wv.y, a.y);
        a.z = fmaf(xv, wv.z, a.z); a.w = fmaf(xv, wv.w, a.w);
    }
    ((float4*)g_partial)[chunk * (QKV_N / 4) + j4] = a;
}

// ======================== reduce partials + fused RoPE ========================
__global__ void reduce_rope_k(int past) {
    int tid = threadIdx.x;
    int e = blockIdx.x * 256 + tid;
    __shared__ float redsum[256];
    __shared__ float ctab[64], stab[64];
    if (tid < 64) {
        float ee = (float)tid / 64.0f;
        float p = __nv_powf(10000.0f, ee);
        float invf = 1.0f / p;
        float ang = (float)past * invf;
        double aa = (double)ang;
        ctab[tid] = (float)cos(aa);
        stab[tid] = (float)sin(aa);
    }
    float s = 0.f;
#pragma unroll 16
    for (int c = 0; c < SPLIT; ++c) s += g_partial[c * QKV_N + e];
    redsum[tid] = s;
    __syncthreads();
    int row = e >> 7, col = e & 127;
    float outv = s;
    if (row < 40) {                       // q rows 0-31, k rows 32-39
        float partner = redsum[tid ^ 64];
        float c = ctab[col & 63], sn = stab[col & 63];
        outv = (col < 64) ? (s * c - partner * sn) : (s * c + partner * sn);
    }
    g_qkv[e] = outv;
}

__global__ void reduce_out_k(float* __restrict__ out) {
    int j = blockIdx.x * 256 + threadIdx.x;
    float s = 0.f;
#pragma unroll 16
    for (int c = 0; c < SPLIT; ++c) s += g_partial[c * QKV_N + j];
    out[j] = s;
}

// ======================== page min/max + Quest score (float4) ========================
__global__ void score_k(const float* __restrict__ kc, int np) {
    int p = blockIdx.x;
    int tid = threadIdx.x;
    if (p == np - 1) {
        if (tid < H_HEADS) g_scores[tid * np + p] = INFINITY;
        return;
    }
    __shared__ float qs[HID];
    __shared__ float kmx[KV_HEADS * DIM];
    __shared__ float kmn[KV_HEADS * DIM];
    for (int i = tid; i < HID / 4; i += 256)
        ((float4*)qs)[i] = ((const float4*)g_qkv)[i];
    {
        const float4* base4 = (const float4*)(kc + (size_t)p * PAGE * 1024) + tid;
        float4 v0 = base4[0];
        float4 mx = v0, mn = v0;
#pragma unroll
        for (int t = 1; t < PAGE; ++t) {
            float4 v = base4[t * 256];
            mx.x = fmaxf(mx.x, v.x); mn.x = fminf(mn.x, v.x);
            mx.y = fmaxf(mx.y, v.y); mn.y = fminf(mn.y, v.y);
            mx.z = fmaxf(mx.z, v.z); mn.z = fminf(mn.z, v.z);
            mx.w = fmaxf(mx.w, v.w); mn.w = fminf(mn.w, v.w);
        }
        ((float4*)kmx)[tid] = mx;
        ((float4*)kmn)[tid] = mn;
    }
    __syncthreads();
    int h = tid >> 3, seg = tid & 7;
    int kv = h >> 2;
    float sum = 0.f;
    int db = seg * 16;
#pragma unroll
    for (int d = 0; d < 16; ++d) {
        float qv = qs[h * DIM + db + d];
        float km = kmx[kv * DIM + db + d];
        float kn = kmn[kv * DIM + db + d];
        sum += qv * (qv >= 0.f ? km : kn);
    }
    sum += __shfl_down_sync(0xffffffffu, sum, 4);
    sum += __shfl_down_sync(0xffffffffu, sum, 2);
    sum += __shfl_down_sync(0xffffffffu, sum, 1);
    if (seg == 0) g_scores[h * np + p] = sum;
}

// ======================== exact top-k via 4-level radix select ========================
// Finds the exact 256th-largest monotone key T per head, emits all u>T, and
// the lowest-index ties at u==T. Same selected SET as jax top_k (order-free).
__global__ void topk_k(int np) {
    int h = blockIdx.x;
    int tid = threadIdx.x;                 // 512 threads
    __shared__ unsigned su[MAXPAGES];
    __shared__ int      ties[MAXPAGES];
    __shared__ unsigned hist[256];
    __shared__ unsigned scan[256];
    __shared__ unsigned bcast[2];
    __shared__ unsigned cnt_gt, tie_cnt;

    for (int i = tid; i < np; i += 512) {
        float f = g_scores[h * np + i];
        unsigned u = __float_as_uint(f);
        su[i] = (u & 0x80000000u) ? ~u : (u | 0x80000000u);
    }
    __syncthreads();

    unsigned prefix = 0, R = TOPK;
#pragma unroll
    for (int level = 0; level < 4; ++level) {
        int shift = 24 - level * 8;
        unsigned mask = (level == 0) ? 0u : (0xFFFFFFFFu << (32 - level * 8));
        if (tid < 256) hist[tid] = 0;
        __syncthreads();
        for (int i = tid; i < np; i += 512) {
            unsigned u = su[i];
            if ((u & mask) == prefix) atomicAdd(&hist[(u >> shift) & 0xFF], 1u);
        }
        __syncthreads();
        // suffix-inclusive scan: scan[b] = sum_{b'>=b} hist[b']
        if (tid < 256) scan[tid] = hist[tid];
        __syncthreads();
#pragma unroll
        for (int off = 1; off < 256; off <<= 1) {
            unsigned v = 0;
            if (tid < 256) { v = scan[tid]; if (tid + off < 256) v += scan[tid + off]; }
            __syncthreads();
            if (tid < 256) scan[tid] = v;
            __syncthreads();
        }
        if (tid < 256) {
            unsigned gt = (tid < 255) ? scan[tid + 1] : 0;   // strictly-greater count
            if (gt < R && gt + hist[tid] >= R) { bcast[0] = (unsigned)tid; bcast[1] = R - gt; }
        }
        __syncthreads();
        prefix |= (bcast[0] << shift);
        R = bcast[1];
        __syncthreads();
    }
    unsigned T = prefix, Rtie = R;

    if (tid == 0) { cnt_gt = 0; tie_cnt = 0; }
    __syncthreads();
    for (int i = tid; i < np; i += 512) {
        unsigned u = su[i];
        if (u > T) {
            unsigned pos = atomicAdd(&cnt_gt, 1u);
            g_topk[h * TOPK + pos] = i;
        } else if (u == T) {
            unsigned tp = atomicAdd(&tie_cnt, 1u);
            ties[tp] = i;
        }
    }
    __syncthreads();

    // sort tie indices ascending (usually tiny; generic bitonic for safety)
    int tcnt = (int)tie_cnt;
    if (tcnt > 1) {
        int n = 1; while (n < tcnt) n <<= 1;
        for (int i = tid; i < n; i += 512) if (i >= tcnt) ties[i] = 0x7FFFFFFF;
        __syncthreads();
        for (int k = 2; k <= n; k <<= 1) {
            for (int j = k >> 1; j > 0; j >>= 1) {
                for (int i = tid; i < n; i += 512) {
                    int ixj = i ^ j;
                    if (ixj > i) {
                        bool up = ((i & k) == 0);
                        int a = ties[i], bb = ties[ixj];
                        if ((a > bb) == up) { ties[i] = bb; ties[ixj] = a; }
                    }
                }
                __syncthreads();
            }
        }
    }
    unsigned base = cnt_gt;                  // == TOPK - Rtie
    if (tid < Rtie) g_topk[h * TOPK + base + tid] = ties[tid];
}

// ======================== flash-decode partial ========================
__global__ void attn_partial_k(const float* __restrict__ kc, const float* __restrict__ vc,
                               int past) {
    int b = blockIdx.x;
    int h = b >> 5, chunk = b & 31;
    int kv = h >> 2;
    int tid = threadIdx.x, w = tid >> 5, lane = tid & 31;
    __shared__ float sc[TPC];
    __shared__ float redm[8];
    __shared__ float redl[8];
    __shared__ float accbuf[8 * DIM];

    const int* tk = g_topk + h * TOPK + chunk * PPC;   // 8 pages = 128 tokens

    {
        int sub = lane & 3, tg = lane >> 2;
        float4 q4[8];
        const float4* qp = (const float4*)(g_qkv + h * DIM);
#pragma unroll
        for (int m = 0; m < 8; ++m) q4[m] = qp[sub + 4 * m];
#pragma unroll
        for (int t = 0; t < 2; ++t) {
            int tw = w * 16 + t * 8 + tg;
            int page = tk[tw >> 4];
            int tok = page * PAGE + (tw & 15);
            const float4* kp = (tok == past)
                ? (const float4*)(g_qkv + 4096 + kv * DIM)
                : (const float4*)(kc + ((size_t)tok * KV_HEADS + kv) * DIM);
            float d = 0.f;
#pragma unroll
            for (int m = 0; m < 8; ++m) {
                float4 k4 = kp[sub + 4 * m];
                d = fmaf(q4[m].x, k4.x, d); d = fmaf(q4[m].y, k4.y, d);
                d = fmaf(q4[m].z, k4.z, d); d = fmaf(q4[m].w, k4.w, d);
            }
            d += __shfl_xor_sync(0xffffffffu, d, 1);
            d += __shfl_xor_sync(0xffffffffu, d, 2);
            if (sub == 0) sc[tw] = d * 0.08838834764831844f;   // 1/sqrt(128)
        }
    }
    __syncthreads();

    float v = (tid < TPC) ? sc[tid] : -INFINITY;
    float m = v;
#pragma unroll
    for (int o = 16; o; o >>= 1) m = fmaxf(m, __shfl_xor_sync(0xffffffffu, m, o));
    if (lane == 0) redm[w] = m;
    __syncthreads();
    if (tid == 0) {
        float mm = redm[0];
#pragma unroll
        for (int i = 1; i < 8; ++i) mm = fmaxf(mm, redm[i]);
        redm[0] = mm;
    }
    __syncthreads();
    float bm = redm[0];

    float e = (tid < TPC) ? __expf(v - bm) : 0.f;
    if (tid < TPC) sc[tid] = e;
    float l = e;
#pragma unroll
    for (int o = 16; o; o >>= 1) l += __shfl_xor_sync(0xffffffffu, l, o);
    if (lane == 0) redl[w] = l;
    __syncthreads();

    float4 acc = make_float4(0.f, 0.f, 0.f, 0.f);
#pragma unroll 4
    for (int s = 0; s < 16; ++s) {
        int tw = w * 16 + s;
        int page = tk[tw >> 4];
        int tok = page * PAGE + (tw & 15);
        const float4* vp = (tok == past)
            ? (const float4*)(g_qkv + 5120 + kv * DIM)
            : (const float4*)(vc + ((size_t)tok * KV_HEADS + kv) * DIM);
        float4 v4 = vp[lane];
        float ee = sc[tw];
        acc.x = fmaf(ee, v4.x, acc.x); acc.y = fmaf(ee, v4.y, acc.y);
        acc.z = fmaf(ee, v4.z, acc.z); acc.w = fmaf(ee, v4.w, acc.w);
    }
    *(float4*)(accbuf + w * DIM + lane * 4) = acc;
    __syncthreads();
    if (tid < DIM) {
        float s = 0.f;
#pragma unroll
        for (int ww = 0; ww < 8; ++ww) s += accbuf[ww * DIM + tid];
        g_acc[(h * NCHUNK + chunk) * DIM + tid] = s;
    }
    if (tid == 0) {
        float L = 0.f;
#pragma unroll
        for (int i = 0; i < 8; ++i) L += redl[i];
        g_m[h * NCHUNK + chunk] = bm;
        g_l[h * NCHUNK + chunk] = L;
    }
}

// ======================== flash-decode combine ========================
__global__ void attn_combine_k() {
    int h = blockIdx.x;
    int d = threadIdx.x;                     // 128
    float M = -INFINITY;
#pragma unroll
    for (int c = 0; c < NCHUNK; ++c) M = fmaxf(M, g_m[h * NCHUNK + c]);
    float L = 0.f, acc = 0.f;
#pragma unroll
    for (int c = 0; c < NCHUNK; ++c) {
        float f = __expf(g_m[h * NCHUNK + c] - M);
        L += f * g_l[h * NCHUNK + c];
        acc += f * g_acc[(h * NCHUNK + c) * DIM + d];
    }
    g_attnout[h * DIM + d] = acc / L;
}

// ======================== launcher ========================
extern "C" void kernel_launch(void* const* d_in, const int* in_sizes, int n_in,
                              void* d_out, int out_size) {
    const float* x  = (const float*)d_in[0];
    const float* kc = (const float*)d_in[1];
    const float* vc = (const float*)d_in[2];
    const float* Wq = (const float*)d_in[3];
    const float* Wk = (const float*)d_in[4];
    const float* Wv = (const float*)d_in[5];
    const float* Wo = (const float*)d_in[6];
    float* out = (float*)d_out;

    int past = in_sizes[1] / (KV_HEADS * DIM);   // 32767
    int np   = (past + 1) / PAGE;                // 2048

    gemv_qkv_k<<<768, 256>>>(Wq, Wk, Wv, x);
    reduce_rope_k<<<QKV_N / 256, 256>>>(past);
    score_k<<<np, 256>>>(kc, np);
    topk_k<<<H_HEADS, 512>>>(np);
    attn_partial_k<<<H_HEADS * NCHUNK, 256>>>(kc, vc, past);
    attn_combine_k<<<H_HEADS, 128>>>();
    gemv_o_k<<<512, 256>>>(Wo);
    reduce_out_k<<<HID / 256, 256>>>(out);
}

// round 6
// speedup vs baseline: 1.4517x; 1.0613x over previous
#include <cuda_runtime.h>
#include <cuda_bf16.h>
#include <math.h>
#include <stdint.h>

#define H_HEADS   32
#define KV_HEADS  8
#define DIM       128
#define PAGE      16
#define TOPK      256
#define HID       4096
#define QKV_N     6144         // 4096 q + 1024 k + 1024 v
#define SPLIT     128          // K-chunks of 32 rows
#define MAXPAGES  2048
#define NCHUNK    32           // flash-decode chunks per head
#define PPC       8            // pages per chunk
#define TPC       128          // tokens per chunk

extern "C" __device__ float __nv_powf(float, float);

// -------- device scratch (symbols only referenced inside kernels!) --------
__device__ float g_partial[SPLIT * QKV_N];
__device__ float g_qkv[QKV_N];                 // [0,4096)=q, [4096,5120)=k, [5120,6144)=v
__device__ float g_scores[H_HEADS * MAXPAGES];
__device__ int   g_topk[H_HEADS * TOPK];
__device__ float g_m[H_HEADS * NCHUNK];
__device__ float g_l[H_HEADS * NCHUNK];
__device__ float g_acc[H_HEADS * NCHUNK * DIM];

// ======================== fused QKV split-K GEMV (float4) ========================
__global__ void gemv_qkv_k(const float* __restrict__ Wq, const float* __restrict__ Wk,
                           const float* __restrict__ Wv, const float* __restrict__ x) {
    int b = blockIdx.x, tid = threadIdx.x;
    const float* W; int N4, xb, chunk, colOff4;
    if (b < 512)      { W = Wq; N4 = 1024; xb = b & 3; chunk = b >> 2;  colOff4 = 0; }
    else if (b < 640) { W = Wk; N4 = 256;  xb = 0;     chunk = b - 512; colOff4 = 1024; }
    else              { W = Wv; N4 = 256;  xb = 0;     chunk = b - 640; colOff4 = 1280; }
    __shared__ float xs[32];
    if (tid < 32) xs[tid] = x[chunk * 32 + tid];
    __syncthreads();
    int j4 = xb * 256 + tid;
    const float4* w4 = (const float4*)W + (size_t)(chunk * 32) * N4 + j4;
    float4 a = make_float4(0.f, 0.f, 0.f, 0.f);
#pragma unroll
    for (int i = 0; i < 32; ++i) {
        float4 wv = w4[(size_t)i * N4];
        float xv = xs[i];
        a.x = fmaf(xv, wv.x, a.x); a.y = fmaf(xv, wv.y, a.y);
        a.z = fmaf(xv, wv.z, a.z); a.w = fmaf(xv, wv.w, a.w);
    }
    ((float4*)g_partial)[chunk * (QKV_N / 4) + colOff4 + j4] = a;
}

// ======================== Wo GEMV with fused flash-decode combine ========================
__global__ void gemv_o_k(const float* __restrict__ Wo) {
    int b = blockIdx.x, tid = threadIdx.x;
    int xb = b & 3, chunk = b >> 2;          // chunk in [0,128)
    __shared__ float xs[32];
    if (tid < 32) {
        int h = chunk >> 2;                  // 4 chunks (32 dims each) per head
        int d = (chunk & 3) * 32 + tid;
        float M = -INFINITY;
#pragma unroll
        for (int c = 0; c < NCHUNK; ++c) M = fmaxf(M, g_m[h * NCHUNK + c]);
        float L = 0.f, acc = 0.f;
#pragma unroll
        for (int c = 0; c < NCHUNK; ++c) {
            float f = __expf(g_m[h * NCHUNK + c] - M);
            L += f * g_l[h * NCHUNK + c];
            acc += f * g_acc[(h * NCHUNK + c) * DIM + d];
        }
        xs[tid] = acc / L;
    }
    __syncthreads();
    int j4 = xb * 256 + tid;
    const float4* w4 = (const float4*)Wo + (size_t)(chunk * 32) * 1024 + j4;
    float4 a = make_float4(0.f, 0.f, 0.f, 0.f);
#pragma unroll
    for (int i = 0; i < 32; ++i) {
        float4 wv = w4[(size_t)i * 1024];
        float xv = xs[i];
        a.x = fmaf(xv, wv.x, a.x); a.y = fmaf(xv, wv.y, a.y);
        a.z = fmaf(xv, wv.z, a.z); a.w = fmaf(xv, wv.w, a.w);
    }
    ((float4*)g_partial)[chunk * (QKV_N / 4) + j4] = a;
}

// ======================== reduce partials + fused RoPE ========================
__global__ void reduce_rope_k(int past) {
    int tid = threadIdx.x;
    int e = blockIdx.x * 256 + tid;
    __shared__ float redsum[256];
    __shared__ float ctab[64], stab[64];
    if (tid < 64) {
        float ee = (float)tid / 64.0f;
        float p = __nv_powf(10000.0f, ee);
        float invf = 1.0f / p;
        float ang = (float)past * invf;
        double aa = (double)ang;
        ctab[tid] = (float)cos(aa);
        stab[tid] = (float)sin(aa);
    }
    float s = 0.f;
#pragma unroll 16
    for (int c = 0; c < SPLIT; ++c) s += g_partial[c * QKV_N + e];
    redsum[tid] = s;
    __syncthreads();
    int row = e >> 7, col = e & 127;
    float outv = s;
    if (row < 40) {                       // q rows 0-31, k rows 32-39
        float partner = redsum[tid ^ 64];
        float c = ctab[col & 63], sn = stab[col & 63];
        outv = (col < 64) ? (s * c - partner * sn) : (s * c + partner * sn);
    }
    g_qkv[e] = outv;
}

__global__ void reduce_out_k(float* __restrict__ out) {
    int j = blockIdx.x * 256 + threadIdx.x;
    float s = 0.f;
#pragma unroll 16
    for (int c = 0; c < SPLIT; ++c) s += g_partial[c * QKV_N + j];
    out[j] = s;
}

// ======================== page min/max + Quest score (4 pages/block) ========================
__global__ void score_k(const float* __restrict__ kc, int np) {
    int tid = threadIdx.x;
    __shared__ float qs[HID];
    __shared__ float kmx[KV_HEADS * DIM];
    __shared__ float kmn[KV_HEADS * DIM];
    for (int i = tid; i < HID / 4; i += 256)
        ((float4*)qs)[i] = ((const float4*)g_qkv)[i];
#pragma unroll
    for (int pg = 0; pg < 4; ++pg) {
        int p = blockIdx.x * 4 + pg;               // block-uniform
        if (p == np - 1) {
            if (tid < H_HEADS) g_scores[tid * np + p] = INFINITY;
            continue;
        }
        {
            const float4* base4 = (const float4*)(kc + (size_t)p * PAGE * 1024) + tid;
            float4 v0 = base4[0];
            float4 mx = v0, mn = v0;
#pragma unroll
            for (int t = 1; t < PAGE; ++t) {
                float4 v = base4[t * 256];
                mx.x = fmaxf(mx.x, v.x); mn.x = fminf(mn.x, v.x);
                mx.y = fmaxf(mx.y, v.y); mn.y = fminf(mn.y, v.y);
                mx.z = fmaxf(mx.z, v.z); mn.z = fminf(mn.z, v.z);
                mx.w = fmaxf(mx.w, v.w); mn.w = fminf(mn.w, v.w);
            }
            ((float4*)kmx)[tid] = mx;
            ((float4*)kmn)[tid] = mn;
        }
        __syncthreads();                           // minmax (and qs on pg 0) ready
        int h = tid >> 3, seg = tid & 7;
        int kv = h >> 2;
        float sum = 0.f;
        int db = seg * 16;
#pragma unroll
        for (int d = 0; d < 16; ++d) {
            float qv = qs[h * DIM + db + d];
            float km = kmx[kv * DIM + db + d];
            float kn = kmn[kv * DIM + db + d];
            sum += qv * (qv >= 0.f ? km : kn);
        }
        sum += __shfl_down_sync(0xffffffffu, sum, 4);
        sum += __shfl_down_sync(0xffffffffu, sum, 2);
        sum += __shfl_down_sync(0xffffffffu, sum, 1);
        if (seg == 0) g_scores[h * np + p] = sum;
        __syncthreads();                           // before next page overwrites kmx/kmn
    }
}

// ======================== exact top-k: radix select, warp-shuffle scan ========================
__global__ void topk_k(int np) {
    int h = blockIdx.x;
    int tid = threadIdx.x;                 // 512 threads
    __shared__ unsigned su[MAXPAGES];
    __shared__ int      ties[64];
    __shared__ unsigned hist[256];
    __shared__ unsigned bcast[2];
    __shared__ unsigned cnt_gt, tie_cnt;

    for (int i = tid; i < np; i += 512) {
        float f = g_scores[h * np + i];
        unsigned u = __float_as_uint(f);
        su[i] = (u & 0x80000000u) ? ~u : (u | 0x80000000u);
    }
    if (tid == 0) { cnt_gt = 0; tie_cnt = 0; }
    __syncthreads();

    unsigned prefix = 0, R = TOPK;
#pragma unroll
    for (int level = 0; level < 4; ++level) {
        int shift = 24 - level * 8;
        unsigned mask = (level == 0) ? 0u : (0xFFFFFFFFu << (32 - level * 8));
        if (tid < 256) hist[tid] = 0;
        __syncthreads();
        for (int i = tid; i < np; i += 512) {
            unsigned u = su[i];
            if ((u & mask) == prefix) atomicAdd(&hist[(u >> shift) & 0xFF], 1u);
        }
        __syncthreads();
        if (tid < 32) {                      // warp 0: suffix scan of 256 bins
            int lane = tid;
            unsigned hb[8];
            unsigned lane_sum = 0;
#pragma unroll
            for (int b = 0; b < 8; ++b) { hb[b] = hist[lane * 8 + b]; lane_sum += hb[b]; }
            unsigned suf = lane_sum;
#pragma unroll
            for (int off = 1; off < 32; off <<= 1) {
                unsigned v = __shfl_down_sync(0xffffffffu, suf, off);
                if (lane + off < 32) suf += v;
            }
            unsigned tail = suf - lane_sum;  // sum of bins owned by lanes > lane
            unsigned cum = 0;
#pragma unroll
            for (int b = 7; b >= 0; --b) {
                cum += hb[b];
                unsigned incl = tail + cum;  // count of keys >= this bin (within prefix)
                unsigned gt = incl - hb[b];  // strictly greater
                if (gt < R && incl >= R) { bcast[0] = (unsigned)(lane * 8 + b); bcast[1] = R - gt; }
            }
        }
        __syncthreads();
        prefix |= (bcast[0] << shift);
        R = bcast[1];
        __syncthreads();
    }
    unsigned T = prefix, Rtie = R;

    for (int i = tid; i < np; i += 512) {
        unsigned u = su[i];
        if (u > T) {
            unsigned pos = atomicAdd(&cnt_gt, 1u);
            g_topk[h * TOPK + pos] = i;
        } else if (u == T) {
            unsigned tp = atomicAdd(&tie_cnt, 1u);
            if (tp < 64) ties[tp] = i;
        }
    }
    __syncthreads();

    // select the Rtie lowest tie indices (tie counts are tiny; insertion via odd-even)
    int tcnt = (int)tie_cnt; if (tcnt > 64) tcnt = 64;
    if (tcnt > 1 && tid < 64) {
        // odd-even transposition sort on <=64 elements using 2 warps
        for (int ph = 0; ph < tcnt; ++ph) {
            int i0 = 2 * tid + (ph & 1);
            int a = (i0 + 1 < tcnt && tid < 32) ? 0 : 0; (void)a;
            if (i0 + 1 < tcnt) {
                int x0 = ties[i0], x1 = ties[i0 + 1];
                if (x0 > x1) { ties[i0] = x1; ties[i0 + 1] = x0; }
            }
            __syncwarp(0xffffffffu);
        }
    }
    __syncthreads();
    unsigned base = cnt_gt;                  // == TOPK - Rtie
    if (tid < Rtie) g_topk[h * TOPK + base + tid] = ties[tid];
}

// ======================== flash-decode partial ========================
__global__ void attn_partial_k(const float* __restrict__ kc, const float* __restrict__ vc,
                               int past) {
    int b = blockIdx.x;
    int h = b >> 5, chunk = b & 31;
    int kv = h >> 2;
    int tid = threadIdx.x, w = tid >> 5, lane = tid & 31;
    __shared__ float sc[TPC];
    __shared__ float redm[8];
    __shared__ float redl[8];
    __shared__ float accbuf[8 * DIM];

    const int* tk = g_topk + h * TOPK + chunk * PPC;   // 8 pages = 128 tokens

    {
        int sub = lane & 3, tg = lane >> 2;
        float4 q4[8];
        const float4* qp = (const float4*)(g_qkv + h * DIM);
#pragma unroll
        for (int m = 0; m < 8; ++m) q4[m] = qp[sub + 4 * m];
#pragma unroll
        for (int t = 0; t < 2; ++t) {
            int tw = w * 16 + t * 8 + tg;
            int page = tk[tw >> 4];
            int tok = page * PAGE + (tw & 15);
            const float4* kp = (tok == past)
                ? (const float4*)(g_qkv + 4096 + kv * DIM)
                : (const float4*)(kc + ((size_t)tok * KV_HEADS + kv) * DIM);
            float d = 0.f;
#pragma unroll
            for (int m = 0; m < 8; ++m) {
                float4 k4 = kp[sub + 4 * m];
                d = fmaf(q4[m].x, k4.x, d); d = fmaf(q4[m].y, k4.y, d);
                d = fmaf(q4[m].z, k4.z, d); d = fmaf(q4[m].w, k4.w, d);
            }
            d += __shfl_xor_sync(0xffffffffu, d, 1);
            d += __shfl_xor_sync(0xffffffffu, d, 2);
            if (sub == 0) sc[tw] = d * 0.08838834764831844f;   // 1/sqrt(128)
        }
    }
    __syncthreads();

    float v = (tid < TPC) ? sc[tid] : -INFINITY;
    float m = v;
#pragma unroll
    for (int o = 16; o; o >>= 1) m = fmaxf(m, __shfl_xor_sync(0xffffffffu, m, o));
    if (lane == 0) redm[w] = m;
    __syncthreads();
    if (tid == 0) {
        float mm = redm[0];
#pragma unroll
        for (int i = 1; i < 8; ++i) mm = fmaxf(mm, redm[i]);
        redm[0] = mm;
    }
    __syncthreads();
    float bm = redm[0];

    float e = (tid < TPC) ? __expf(v - bm) : 0.f;
    if (tid < TPC) sc[tid] = e;
    float l = e;
#pragma unroll
    for (int o = 16; o; o >>= 1) l += __shfl_xor_sync(0xffffffffu, l, o);
    if (lane == 0) redl[w] = l;
    __syncthreads();

    float4 acc = make_float4(0.f, 0.f, 0.f, 0.f);
#pragma unroll 4
    for (int s = 0; s < 16; ++s) {
        int tw = w * 16 + s;
        int page = tk[tw >> 4];
        int tok = page * PAGE + (tw & 15);
        const float4* vp = (tok == past)
            ? (const float4*)(g_qkv + 5120 + kv * DIM)
            : (const float4*)(vc + ((size_t)tok * KV_HEADS + kv) * DIM);
        float4 v4 = vp[lane];
        float ee = sc[tw];
        acc.x = fmaf(ee, v4.x, acc.x); acc.y = fmaf(ee, v4.y, acc.y);
        acc.z = fmaf(ee, v4.z, acc.z); acc.w = fmaf(ee, v4.w, acc.w);
    }
    *(float4*)(accbuf + w * DIM + lane * 4) = acc;
    __syncthreads();
    if (tid < DIM) {
        float s = 0.f;
#pragma unroll
        for (int ww = 0; ww < 8; ++ww) s += accbuf[ww * DIM + tid];
        g_acc[(h * NCHUNK + chunk) * DIM + tid] = s;
    }
    if (tid == 0) {
        float L = 0.f;
#pragma unroll
        for (int i = 0; i < 8; ++i) L += redl[i];
        g_m[h * NCHUNK + chunk] = bm;
        g_l[h * NCHUNK + chunk] = L;
    }
}

// ======================== launcher ========================
extern "C" void kernel_launch(void* const* d_in, const int* in_sizes, int n_in,
                              void* d_out, int out_size) {
    const float* x  = (const float*)d_in[0];
    const float* kc = (const float*)d_in[1];
    const float* vc = (const float*)d_in[2];
    const float* Wq = (const float*)d_in[3];
    const float* Wk = (const float*)d_in[4];
    const float* Wv = (const float*)d_in[5];
    const float* Wo = (const float*)d_in[6];
    float* out = (float*)d_out;

    int past = in_sizes[1] / (KV_HEADS * DIM);   // 32767
    int np   = (past + 1) / PAGE;                // 2048

    gemv_qkv_k<<<768, 256>>>(Wq, Wk, Wv, x);
    reduce_rope_k<<<QKV_N / 256, 256>>>(past);
    score_k<<<np / 4, 256>>>(kc, np);
    topk_k<<<H_HEADS, 512>>>(np);
    attn_partial_k<<<H_HEADS * NCHUNK, 256>>>(kc, vc, past);
    gemv_o_k<<<512, 256>>>(Wo);
    reduce_out_k<<<HID / 256, 256>>>(out);
}